// round 10
// baseline (speedup 1.0000x reference)
#include <cuda_runtime.h>
#include <math.h>

#define BATCH 16
#define NP 6
#define NPTS 262144
#define V4PB (NPTS/4)                  // 65536 float4 per batch row (2^16)
#define TOTV4 ((size_t)BATCH * V4PB)   // 1,048,576
#define GRID 740                       // 5 CTAs/SM * 148 SMs, one full wave
#define TPB 256

__device__ __forceinline__ float sqrt_approx(float x) {
    float s; asm("sqrt.approx.f32 %0,%1;" : "=f"(s) : "f"(x)); return s;
}

// Scratch (device globals — no allocation allowed)
__device__ float g_partial[GRID*NP];

// gamma^(P-1-p) for p=0..5, gamma=0.8
__device__ __constant__ float W_GAMMA[NP] =
    {0.32768f, 0.4096f, 0.512f, 0.64f, 0.8f, 1.0f};

// q_rel = conj(q_p) (x) q_t for (p,b).
__device__ __forceinline__ void qrel(const float* __restrict__ tq,
                                     const float* __restrict__ rq,
                                     int p, int b,
                                     float& w, float& x, float& y, float& z)
{
    float t0 = tq[b*4+0], t1 = tq[b*4+1], t2 = tq[b*4+2], t3 = tq[b*4+3];
    float rn = rsqrtf(t0*t0 + t1*t1 + t2*t2 + t3*t3);
    t0 *= rn; t1 *= rn; t2 *= rn; t3 *= rn;

    const float* q = rq + (size_t)(p*BATCH + b)*4;
    float a0 = q[0], a1 = q[1], a2 = q[2], a3 = q[3];
    rn = rsqrtf(a0*a0 + a1*a1 + a2*a2 + a3*a3);
    a0 *= rn; a1 = -a1*rn; a2 = -a2*rn; a3 = -a3*rn;   // conj, normalized

    w = a0*t0 - a1*t1 - a2*t2 - a3*t3;
    x = a0*t1 + a1*t0 + a2*t3 - a3*t2;
    y = a0*t2 - a1*t3 + a2*t0 + a3*t1;
    z = a0*t3 + a1*t2 - a2*t1 + a3*t0;
}

// ---------------------------------------------------------------------------
// Persistent kernel: exactly one full wave at 5 CTAs/SM; each block a
// contiguous balanced v4-range. 96 (b,p) constants in shared; c applied at
// segment flush.
// ---------------------------------------------------------------------------
__global__ __launch_bounds__(TPB, 5)
void pc_kernel(const float* __restrict__ pc,
               const float* __restrict__ tq,
               const float* __restrict__ rq)
{
    // constants: [b][p][4] = ux, uy, uz, c
    __shared__ float s_cst[BATCH*NP*4];
    int tid = threadIdx.x;

    if (tid < BATCH*NP) {
        int b = tid / NP, p = tid - b*NP;
        float w, x, y, z;
        qrel(tq, rq, p, b, w, x, y, z);
        float vn = sqrtf(x*x + y*y + z*z);
        float inv = (vn > 1e-20f) ? (1.0f / vn) : 0.0f;
        float* dst = &s_cst[(b*NP + p)*4];
        dst[0] = (vn > 1e-20f) ? x*inv : 1.0f;
        dst[1] = y*inv;
        dst[2] = z*inv;
        dst[3] = 2.0f * vn;
    }
    __syncthreads();

    size_t vstart = (size_t)blockIdx.x       * TOTV4 / GRID;
    size_t vend   = (size_t)(blockIdx.x + 1) * TOTV4 / GRID;

    float blk_acc[NP];
#pragma unroll
    for (int p = 0; p < NP; ++p) blk_acc[p] = 0.0f;

    size_t v = vstart;
    while (v < vend) {
        int b = (int)(v >> 16);                       // V4PB = 2^16
        size_t segend = ((size_t)(b + 1)) << 16;
        if (segend > vend) segend = vend;

        const float4* base = (const float4*)pc + (size_t)b * (4*V4PB);
        float ux[NP], uy[NP], uz[NP];
#pragma unroll
        for (int p = 0; p < NP; ++p) {
            const float* c4 = &s_cst[(b*NP + p)*4];
            ux[p] = c4[0]; uy[p] = c4[1]; uz[p] = c4[2];
        }

        float seg[NP];
#pragma unroll
        for (int p = 0; p < NP; ++p) seg[p] = 0.0f;

        size_t woff = (size_t)b << 16;                // subtract to index base
#pragma unroll 4
        for (size_t i = v + tid; i < segend; i += TPB) {
            size_t w = i - woff;
            float4 X = base[w];
            float4 Y = base[w + V4PB];
            float4 Z = base[w + 2*V4PB];
            float xs[4] = {X.x, X.y, X.z, X.w};
            float ys[4] = {Y.x, Y.y, Y.z, Y.w};
            float zs[4] = {Z.x, Z.y, Z.z, Z.w};
#pragma unroll
            for (int l = 0; l < 4; ++l) {
                float x = xs[l], y = ys[l], z = zs[l];
                float r2 = fmaf(x, x, fmaf(y, y, z*z));
#pragma unroll
                for (int p = 0; p < NP; ++p) {
                    float d = fmaf(ux[p], x, fmaf(uy[p], y, uz[p]*z));
                    float t = fmaxf(fmaf(-d, d, r2), 0.0f);
                    seg[p] += sqrt_approx(t);
                }
            }
        }

        // flush segment: apply c for this b
#pragma unroll
        for (int p = 0; p < NP; ++p)
            blk_acc[p] = fmaf(s_cst[(b*NP + p)*4 + 3], seg[p], blk_acc[p]);

        v = segend;
    }

    // block reduction: warp shfl then cross-warp via shared
#pragma unroll
    for (int p = 0; p < NP; ++p)
#pragma unroll
        for (int off = 16; off > 0; off >>= 1)
            blk_acc[p] += __shfl_down_sync(0xffffffffu, blk_acc[p], off);

    __shared__ float sh[TPB/32][NP];
    int warp = tid >> 5, lane = tid & 31;
    if (lane == 0) {
#pragma unroll
        for (int p = 0; p < NP; ++p) sh[warp][p] = blk_acc[p];
    }
    __syncthreads();
    if (tid < NP) {
        float s = 0.0f;
#pragma unroll
        for (int wi = 0; wi < TPB/32; ++wi) s += sh[wi][tid];
        g_partial[blockIdx.x*NP + tid] = s;
    }
}

// ---------------------------------------------------------------------------
// Final: sum 740 partials per p (L2 resident) + rot losses + combine.
// ---------------------------------------------------------------------------
__global__ void final_kernel(const float* __restrict__ tq,
                             const float* __restrict__ rq,
                             float* __restrict__ out)
{
    __shared__ float sh64[NP][64];
    __shared__ float s_pcl[NP];
    __shared__ float s_rot[NP*BATCH];
    int t = threadIdx.x;

    if (t < NP*64) {                        // 384 threads
        int p = t >> 6, k = t & 63;
        float s = 0.0f;
        for (int j = k; j < GRID; j += 64)  // 11-12 loads each
            s += __ldcg(&g_partial[j*NP + p]);
        sh64[p][k] = s;
    }
    if (t >= 384 && t < 384 + NP*BATCH) {   // 96 threads for rot
        int g = t - 384;
        int p = g / BATCH, bb = g - p*BATCH;
        float w, x, y, z;
        qrel(tq, rq, p, bb, w, x, y, z);
        s_rot[g] = 2.0f * atan2f(sqrtf(x*x + y*y + z*z), fabsf(w));
    }
    __syncthreads();

    if (t < NP) {
        float s = 0.0f;
#pragma unroll
        for (int k = 0; k < 64; ++k) s += sh64[t][k];
        s_pcl[t] = s * (1.0f / (float)NPTS);
    }
    __syncthreads();

    if (t == 0) {
        float total = 0.0f, rl = 0.0f, pl = 0.0f;
#pragma unroll
        for (int p = 0; p < NP; ++p) {
            float rot = 0.0f;
#pragma unroll
            for (int bb = 0; bb < BATCH; ++bb) rot += s_rot[p*BATCH + bb];
            rot *= (1.0f / (float)BATCH);
            float pclB = s_pcl[p] * (1.0f / (float)BATCH);
            float wgt = W_GAMMA[p];
            total += wgt * (0.5f * rot + 0.5f * pclB);
            rl    += wgt * rot;
            pl    += wgt * pclB;
        }
        out[0] = total; out[1] = rl; out[2] = pl;
    }
}

extern "C" void kernel_launch(void* const* d_in, const int* in_sizes, int n_in,
                              void* d_out, int out_size)
{
    (void)in_sizes; (void)n_in; (void)out_size;
    const float* pc = (const float*)d_in[0];   // point_clouds [B,4,N]
    // d_in[1] = target_transl (cancels analytically — unused)
    const float* tr = (const float*)d_in[2];   // target_rot [B,4]
    const float* rl = (const float*)d_in[3];   // rot_list [P,B,4]

    pc_kernel   <<<GRID, TPB>>>(pc, tr, rl);
    final_kernel<<<1, 480>>>(tr, rl, (float*)d_out);
}

// round 11
// speedup vs baseline: 1.1928x; 1.1928x over previous
#include <cuda_runtime.h>
#include <math.h>

#define BATCH 16
#define NP 6
#define NPTS 262144
#define BPB 64                          // blocks per batch element
#define NBLOCKS (BATCH*BPB)             // 1024
#define TPB 256
#define PTS_PER_BLOCK (NPTS/BPB)        // 4096
#define V4_PER_BLOCK (PTS_PER_BLOCK/4)  // 1024

typedef unsigned long long u64;

// ---- packed f32x2 helpers (sm_103a) ---------------------------------------
__device__ __forceinline__ u64 pk2(float lo, float hi) {
    u64 r; asm("mov.b64 %0,{%1,%2};" : "=l"(r) : "f"(lo), "f"(hi)); return r;
}
__device__ __forceinline__ void up2(u64 v, float& lo, float& hi) {
    asm("mov.b64 {%0,%1},%2;" : "=f"(lo), "=f"(hi) : "l"(v));
}
__device__ __forceinline__ u64 fma2_(u64 a, u64 b, u64 c) {
    u64 r; asm("fma.rn.f32x2 %0,%1,%2,%3;" : "=l"(r) : "l"(a), "l"(b), "l"(c)); return r;
}
__device__ __forceinline__ u64 mul2_(u64 a, u64 b) {
    u64 r; asm("mul.rn.f32x2 %0,%1,%2;" : "=l"(r) : "l"(a), "l"(b)); return r;
}
__device__ __forceinline__ u64 add2_(u64 a, u64 b) {
    u64 r; asm("add.rn.f32x2 %0,%1,%2;" : "=l"(r) : "l"(a), "l"(b)); return r;
}
__device__ __forceinline__ float sqrt_approx(float x) {
    float s; asm("sqrt.approx.f32 %0,%1;" : "=f"(s) : "f"(x)); return s;
}

// Scratch (device globals — no allocation allowed)
__device__ float g_partial[NBLOCKS*NP];   // c-scaled per-block sums

// gamma^(P-1-p) for p=0..5, gamma=0.8
__device__ __constant__ float W_GAMMA[NP] =
    {0.32768f, 0.4096f, 0.512f, 0.64f, 0.8f, 1.0f};

// q_rel = conj(q_p) (x) q_t for (p,b).
__device__ __forceinline__ void qrel(const float* __restrict__ tq,
                                     const float* __restrict__ rq,
                                     int p, int b,
                                     float& w, float& x, float& y, float& z)
{
    float t0 = tq[b*4+0], t1 = tq[b*4+1], t2 = tq[b*4+2], t3 = tq[b*4+3];
    float rn = rsqrtf(t0*t0 + t1*t1 + t2*t2 + t3*t3);
    t0 *= rn; t1 *= rn; t2 *= rn; t3 *= rn;

    const float* q = rq + (size_t)(p*BATCH + b)*4;
    float a0 = q[0], a1 = q[1], a2 = q[2], a3 = q[3];
    rn = rsqrtf(a0*a0 + a1*a1 + a2*a2 + a3*a3);
    a0 *= rn; a1 = -a1*rn; a2 = -a2*rn; a3 = -a3*rn;   // conj, normalized

    w = a0*t0 - a1*t1 - a2*t2 - a3*t3;
    x = a0*t1 + a1*t0 + a2*t3 - a3*t2;
    y = a0*t2 - a1*t3 + a2*t0 + a3*t1;
    z = a0*t3 + a1*t2 - a2*t1 + a3*t0;
}

// ---------------------------------------------------------------------------
// Main kernel — R2 configuration verbatim (best measured), with streaming
// cache hints on the point loads.
// ---------------------------------------------------------------------------
__global__ __launch_bounds__(TPB)
void pc_kernel(const float* __restrict__ pc,
               const float* __restrict__ tq,
               const float* __restrict__ rq)
{
    int blk   = blockIdx.x;
    int b     = blk >> 6;               // / BPB
    int chunk = blk & (BPB - 1);

    __shared__ float s_ux[NP], s_uy[NP], s_uz[NP], s_c[NP];

    if (threadIdx.x < NP) {
        int p = threadIdx.x;
        float w, x, y, z;
        qrel(tq, rq, p, b, w, x, y, z);
        float vn = sqrtf(x*x + y*y + z*z);
        if (vn > 1e-20f) {
            float inv = 1.0f / vn;
            s_ux[p] = x*inv; s_uy[p] = y*inv; s_uz[p] = z*inv;
            s_c[p]  = 2.0f * vn;
        } else {
            s_ux[p] = 1.0f; s_uy[p] = 0.0f; s_uz[p] = 0.0f; s_c[p] = 0.0f;
        }
    }
    __syncthreads();

    u64 ux2[NP], uy2[NP], uz2[NP];
#pragma unroll
    for (int p = 0; p < NP; ++p) {
        ux2[p] = pk2(s_ux[p], s_ux[p]);
        uy2[p] = pk2(s_uy[p], s_uy[p]);
        uz2[p] = pk2(s_uz[p], s_uz[p]);
    }

    const size_t base = (size_t)b * 4 * NPTS + (size_t)chunk * PTS_PER_BLOCK;
    const float4* xr = (const float4*)(pc + base);
    const float4* yr = (const float4*)(pc + base + NPTS);
    const float4* zr = (const float4*)(pc + base + 2*NPTS);

    u64 acc2[NP];
#pragma unroll
    for (int p = 0; p < NP; ++p) acc2[p] = 0ull;

    const u64 SGN = 0x8000000080000000ULL;

#pragma unroll 4
    for (int i = threadIdx.x; i < V4_PER_BLOCK; i += TPB) {
        float4 X = __ldcs(xr + i);
        float4 Y = __ldcs(yr + i);
        float4 Z = __ldcs(zr + i);
#pragma unroll
        for (int j = 0; j < 2; ++j) {
            u64 x = (j == 0) ? pk2(X.x, X.y) : pk2(X.z, X.w);
            u64 y = (j == 0) ? pk2(Y.x, Y.y) : pk2(Y.z, Y.w);
            u64 z = (j == 0) ? pk2(Z.x, Z.y) : pk2(Z.z, Z.w);
            u64 r2 = fma2_(x, x, fma2_(y, y, mul2_(z, z)));
#pragma unroll
            for (int p = 0; p < NP; ++p) {
                u64 d  = fma2_(ux2[p], x, fma2_(uy2[p], y, mul2_(uz2[p], z)));
                u64 nd = d ^ SGN;                    // ALU pipe (idle)
                u64 t  = fma2_(nd, d, r2);           // r2 - d^2 (packed)
                float t0, t1; up2(t, t0, t1);
                float s0 = sqrt_approx(fmaxf(t0, 0.0f));
                float s1 = sqrt_approx(fmaxf(t1, 0.0f));
                acc2[p] = add2_(acc2[p], pk2(s0, s1));
            }
        }
    }

    // collapse packed halves, warp reduce, cross-warp via shared
    float acc[NP];
#pragma unroll
    for (int p = 0; p < NP; ++p) {
        float lo, hi; up2(acc2[p], lo, hi);
        acc[p] = lo + hi;
#pragma unroll
        for (int off = 16; off > 0; off >>= 1)
            acc[p] += __shfl_down_sync(0xffffffffu, acc[p], off);
    }

    __shared__ float sh[TPB/32][NP];
    int warp = threadIdx.x >> 5, lane = threadIdx.x & 31;
    if (lane == 0) {
#pragma unroll
        for (int p = 0; p < NP; ++p) sh[warp][p] = acc[p];
    }
    __syncthreads();
    if (threadIdx.x < NP) {
        int p = threadIdx.x;
        float s = 0.0f;
#pragma unroll
        for (int wi = 0; wi < TPB/32; ++wi) s += sh[wi][p];
        g_partial[blk*NP + p] = s * s_c[p];          // apply c here
    }
}

// ---------------------------------------------------------------------------
// Final: 384 threads; 4-way split of the 64-partial sums (L2 resident).
// ---------------------------------------------------------------------------
__global__ void final_kernel(const float* __restrict__ tq,
                             const float* __restrict__ rq,
                             float* __restrict__ out)
{
    __shared__ float sh4[NP*BATCH][4];
    __shared__ float s_pcl[NP*BATCH];
    __shared__ float s_rot[NP*BATCH];
    int t = threadIdx.x;

    if (t < 4*NP*BATCH) {                 // 384 threads
        int g = t >> 2, k = t & 3;
        int p = g / BATCH, bb = g % BATCH;
        float s = 0.0f;
#pragma unroll
        for (int j = 0; j < BPB/4; ++j)   // 16 each
            s += __ldcg(&g_partial[((size_t)bb*BPB + k*(BPB/4) + j)*NP + p]);
        sh4[g][k] = s;
    }
    __syncthreads();

    if (t < NP*BATCH) {
        int p = t / BATCH, bb = t % BATCH;
        s_pcl[t] = (sh4[t][0] + sh4[t][1] + sh4[t][2] + sh4[t][3])
                   * (1.0f / (float)NPTS);
        float w, x, y, z;
        qrel(tq, rq, p, bb, w, x, y, z);
        s_rot[t] = 2.0f * atan2f(sqrtf(x*x + y*y + z*z), fabsf(w));
    }
    __syncthreads();

    if (t == 0) {
        float total = 0.0f, rl = 0.0f, pl = 0.0f;
#pragma unroll
        for (int p = 0; p < NP; ++p) {
            float pcl = 0.0f, rot = 0.0f;
#pragma unroll
            for (int bb = 0; bb < BATCH; ++bb) {
                pcl += s_pcl[p*BATCH + bb];
                rot += s_rot[p*BATCH + bb];
            }
            rot *= (1.0f / (float)BATCH);
            float pclB = pcl * (1.0f / (float)BATCH);
            float wgt = W_GAMMA[p];
            total += wgt * (0.5f * rot + 0.5f * pclB);
            rl    += wgt * rot;
            pl    += wgt * pclB;
        }
        out[0] = total; out[1] = rl; out[2] = pl;
    }
}

extern "C" void kernel_launch(void* const* d_in, const int* in_sizes, int n_in,
                              void* d_out, int out_size)
{
    (void)in_sizes; (void)n_in; (void)out_size;
    const float* pc = (const float*)d_in[0];   // point_clouds [B,4,N]
    // d_in[1] = target_transl (cancels analytically — unused)
    const float* tr = (const float*)d_in[2];   // target_rot [B,4]
    const float* rl = (const float*)d_in[3];   // rot_list [P,B,4]

    pc_kernel   <<<NBLOCKS, TPB>>>(pc, tr, rl);
    final_kernel<<<1, 384>>>(tr, rl, (float*)d_out);
}

// round 12
// speedup vs baseline: 1.2073x; 1.0122x over previous
#include <cuda_runtime.h>
#include <math.h>

#define BATCH 16
#define NP 6
#define NPTS 262144
#define BPB 64                          // blocks per batch element
#define NBLOCKS (BATCH*BPB)             // 1024
#define TPB 256
#define PTS_PER_BLOCK (NPTS/BPB)        // 4096
#define V4_PER_BLOCK (PTS_PER_BLOCK/4)  // 1024

typedef unsigned long long u64;

// ---- packed f32x2 helpers (sm_103a) ---------------------------------------
__device__ __forceinline__ u64 pk2(float lo, float hi) {
    u64 r; asm("mov.b64 %0,{%1,%2};" : "=l"(r) : "f"(lo), "f"(hi)); return r;
}
__device__ __forceinline__ void up2(u64 v, float& lo, float& hi) {
    asm("mov.b64 {%0,%1},%2;" : "=f"(lo), "=f"(hi) : "l"(v));
}
__device__ __forceinline__ u64 fma2_(u64 a, u64 b, u64 c) {
    u64 r; asm("fma.rn.f32x2 %0,%1,%2,%3;" : "=l"(r) : "l"(a), "l"(b), "l"(c)); return r;
}
__device__ __forceinline__ u64 mul2_(u64 a, u64 b) {
    u64 r; asm("mul.rn.f32x2 %0,%1,%2;" : "=l"(r) : "l"(a), "l"(b)); return r;
}
__device__ __forceinline__ float sqrt_approx(float x) {
    float s; asm("sqrt.approx.f32 %0,%1;" : "=f"(s) : "f"(x)); return s;
}

// Scratch (device globals — no allocation allowed)
__device__ float g_partial[NBLOCKS*NP];   // c-scaled per-block sums

// gamma^(P-1-p) for p=0..5, gamma=0.8
__device__ __constant__ float W_GAMMA[NP] =
    {0.32768f, 0.4096f, 0.512f, 0.64f, 0.8f, 1.0f};

// q_rel = conj(q_p) (x) q_t for (p,b).
__device__ __forceinline__ void qrel(const float* __restrict__ tq,
                                     const float* __restrict__ rq,
                                     int p, int b,
                                     float& w, float& x, float& y, float& z)
{
    float t0 = tq[b*4+0], t1 = tq[b*4+1], t2 = tq[b*4+2], t3 = tq[b*4+3];
    float rn = rsqrtf(t0*t0 + t1*t1 + t2*t2 + t3*t3);
    t0 *= rn; t1 *= rn; t2 *= rn; t3 *= rn;

    const float* q = rq + (size_t)(p*BATCH + b)*4;
    float a0 = q[0], a1 = q[1], a2 = q[2], a3 = q[3];
    rn = rsqrtf(a0*a0 + a1*a1 + a2*a2 + a3*a3);
    a0 *= rn; a1 = -a1*rn; a2 = -a2*rn; a3 = -a3*rn;   // conj, normalized

    w = a0*t0 - a1*t1 - a2*t2 - a3*t3;
    x = a0*t1 + a1*t0 + a2*t3 - a3*t2;
    y = a0*t2 - a1*t3 + a2*t0 + a3*t1;
    z = a0*t3 + a1*t2 - a2*t1 + a3*t0;
}

// ---------------------------------------------------------------------------
// Main kernel: R2 shape; loads land pre-packed (ulonglong2), split scalar
// accumulators — strips the pack/unpack MOV tax from the hot loop.
// ---------------------------------------------------------------------------
__global__ __launch_bounds__(TPB)
void pc_kernel(const float* __restrict__ pc,
               const float* __restrict__ tq,
               const float* __restrict__ rq)
{
    int blk   = blockIdx.x;
    int b     = blk >> 6;               // / BPB
    int chunk = blk & (BPB - 1);

    __shared__ float s_ux[NP], s_uy[NP], s_uz[NP], s_c[NP];

    if (threadIdx.x < NP) {
        int p = threadIdx.x;
        float w, x, y, z;
        qrel(tq, rq, p, b, w, x, y, z);
        float vn = sqrtf(x*x + y*y + z*z);
        if (vn > 1e-20f) {
            float inv = 1.0f / vn;
            s_ux[p] = x*inv; s_uy[p] = y*inv; s_uz[p] = z*inv;
            s_c[p]  = 2.0f * vn;
        } else {
            s_ux[p] = 1.0f; s_uy[p] = 0.0f; s_uz[p] = 0.0f; s_c[p] = 0.0f;
        }
    }
    __syncthreads();

    u64 ux2[NP], uy2[NP], uz2[NP];
#pragma unroll
    for (int p = 0; p < NP; ++p) {
        ux2[p] = pk2(s_ux[p], s_ux[p]);
        uy2[p] = pk2(s_uy[p], s_uy[p]);
        uz2[p] = pk2(s_uz[p], s_uz[p]);
    }

    const size_t base = (size_t)b * 4 * NPTS + (size_t)chunk * PTS_PER_BLOCK;
    const ulonglong2* xr = (const ulonglong2*)(pc + base);            // pre-packed pairs
    const ulonglong2* yr = (const ulonglong2*)(pc + base + NPTS);
    const ulonglong2* zr = (const ulonglong2*)(pc + base + 2*NPTS);

    float accLo[NP], accHi[NP];
#pragma unroll
    for (int p = 0; p < NP; ++p) { accLo[p] = 0.0f; accHi[p] = 0.0f; }

    const u64 SGN = 0x8000000080000000ULL;

#pragma unroll 4
    for (int i = threadIdx.x; i < V4_PER_BLOCK; i += TPB) {
        ulonglong2 Xp = xr[i];           // .x = (x0,x1), .y = (x2,x3) packed
        ulonglong2 Yp = yr[i];
        ulonglong2 Zp = zr[i];
#pragma unroll
        for (int j = 0; j < 2; ++j) {
            u64 x = (j == 0) ? Xp.x : Xp.y;
            u64 y = (j == 0) ? Yp.x : Yp.y;
            u64 z = (j == 0) ? Zp.x : Zp.y;
            u64 r2 = fma2_(x, x, fma2_(y, y, mul2_(z, z)));
#pragma unroll
            for (int p = 0; p < NP; ++p) {
                u64 d  = fma2_(ux2[p], x, fma2_(uy2[p], y, mul2_(uz2[p], z)));
                u64 nd = d ^ SGN;                    // ALU pipe (idle)
                u64 t  = fma2_(nd, d, r2);           // r2 - d^2 (packed)
                float t0, t1; up2(t, t0, t1);
                accLo[p] += sqrt_approx(fmaxf(t0, 0.0f));
                accHi[p] += sqrt_approx(fmaxf(t1, 0.0f));
            }
        }
    }

    // collapse halves, warp reduce, cross-warp via shared
    float acc[NP];
#pragma unroll
    for (int p = 0; p < NP; ++p) {
        acc[p] = accLo[p] + accHi[p];
#pragma unroll
        for (int off = 16; off > 0; off >>= 1)
            acc[p] += __shfl_down_sync(0xffffffffu, acc[p], off);
    }

    __shared__ float sh[TPB/32][NP];
    int warp = threadIdx.x >> 5, lane = threadIdx.x & 31;
    if (lane == 0) {
#pragma unroll
        for (int p = 0; p < NP; ++p) sh[warp][p] = acc[p];
    }
    __syncthreads();
    if (threadIdx.x < NP) {
        int p = threadIdx.x;
        float s = 0.0f;
#pragma unroll
        for (int wi = 0; wi < TPB/32; ++wi) s += sh[wi][p];
        g_partial[blk*NP + p] = s * s_c[p];          // apply c here
    }
}

// ---------------------------------------------------------------------------
// Final: 384 threads; 4-way split of the 64-partial sums (L2 resident).
// ---------------------------------------------------------------------------
__global__ void final_kernel(const float* __restrict__ tq,
                             const float* __restrict__ rq,
                             float* __restrict__ out)
{
    __shared__ float sh4[NP*BATCH][4];
    __shared__ float s_pcl[NP*BATCH];
    __shared__ float s_rot[NP*BATCH];
    int t = threadIdx.x;

    if (t < 4*NP*BATCH) {                 // 384 threads
        int g = t >> 2, k = t & 3;
        int p = g / BATCH, bb = g % BATCH;
        float s = 0.0f;
#pragma unroll
        for (int j = 0; j < BPB/4; ++j)   // 16 each
            s += __ldcg(&g_partial[((size_t)bb*BPB + k*(BPB/4) + j)*NP + p]);
        sh4[g][k] = s;
    }
    __syncthreads();

    if (t < NP*BATCH) {
        int p = t / BATCH, bb = t % BATCH;
        s_pcl[t] = (sh4[t][0] + sh4[t][1] + sh4[t][2] + sh4[t][3])
                   * (1.0f / (float)NPTS);
        float w, x, y, z;
        qrel(tq, rq, p, bb, w, x, y, z);
        s_rot[t] = 2.0f * atan2f(sqrtf(x*x + y*y + z*z), fabsf(w));
    }
    __syncthreads();

    if (t == 0) {
        float total = 0.0f, rl = 0.0f, pl = 0.0f;
#pragma unroll
        for (int p = 0; p < NP; ++p) {
            float pcl = 0.0f, rot = 0.0f;
#pragma unroll
            for (int bb = 0; bb < BATCH; ++bb) {
                pcl += s_pcl[p*BATCH + bb];
                rot += s_rot[p*BATCH + bb];
            }
            rot *= (1.0f / (float)BATCH);
            float pclB = pcl * (1.0f / (float)BATCH);
            float wgt = W_GAMMA[p];
            total += wgt * (0.5f * rot + 0.5f * pclB);
            rl    += wgt * rot;
            pl    += wgt * pclB;
        }
        out[0] = total; out[1] = rl; out[2] = pl;
    }
}

extern "C" void kernel_launch(void* const* d_in, const int* in_sizes, int n_in,
                              void* d_out, int out_size)
{
    (void)in_sizes; (void)n_in; (void)out_size;
    const float* pc = (const float*)d_in[0];   // point_clouds [B,4,N]
    // d_in[1] = target_transl (cancels analytically — unused)
    const float* tr = (const float*)d_in[2];   // target_rot [B,4]
    const float* rl = (const float*)d_in[3];   // rot_list [P,B,4]

    pc_kernel   <<<NBLOCKS, TPB>>>(pc, tr, rl);
    final_kernel<<<1, 384>>>(tr, rl, (float*)d_out);
}